// round 1
// baseline (speedup 1.0000x reference)
#include <cuda_runtime.h>
#include <math.h>

#define Bn 16
#define Ln 4096
#define Cn 1024
#define Kn 16
#define NSPLIT 32
#define CHUNK 128          // Ln / NSPLIT
#define THREADS 256
#define NEG_INF (__int_as_float(0xff800000))

// Scratch (allocation-free rule: __device__ globals)
__device__ float g_acc[(size_t)Bn * NSPLIT * Kn * Cn];   // 32 MB partial pooled
__device__ float g_m[Bn * NSPLIT * Kn];                  // partial max
__device__ float g_d[Bn * NSPLIT * Kn];                  // partial exp-sum

// ---- packed dual-fp32 helpers (Blackwell f32x2) ----
__device__ __forceinline__ unsigned long long fma2(unsigned long long a,
                                                   unsigned long long b,
                                                   unsigned long long c) {
    unsigned long long d;
    asm("fma.rn.f32x2 %0, %1, %2, %3;" : "=l"(d) : "l"(a), "l"(b), "l"(c));
    return d;
}
__device__ __forceinline__ float2 unpack2(unsigned long long v) {
    float2 f;
    f.x = __uint_as_float((unsigned int)(v & 0xffffffffULL));
    f.y = __uint_as_float((unsigned int)(v >> 32));
    return f;
}
__device__ __forceinline__ unsigned long long pack2(float a, float b) {
    unsigned long long v;
    asm("mov.b64 %0, {%1, %2};" : "=l"(v) : "f"(a), "f"(b));
    return v;
}

// SMEM layout (dynamic): q staged (64KB) + scores (8KB) + packed weights (16KB) + mask (512B)
#define SMEM_Q     0
#define SMEM_S     (Kn * Cn * 4)                 // 65536
#define SMEM_W2    (SMEM_S + Kn * CHUNK * 4)     // 65536 + 8192 = 73728 (16B aligned)
#define SMEM_MASK  (SMEM_W2 + CHUNK * Kn * 8)    // 73728 + 16384 = 90112
#define SMEM_TOTAL (SMEM_MASK + CHUNK * 4)       // 90624

extern "C" __global__ void __launch_bounds__(THREADS, 1)
pool_partial_kernel(const float* __restrict__ x,
                    const int* __restrict__ mask,
                    const float* __restrict__ q) {
    extern __shared__ char smem[];
    float* qs = (float*)(smem + SMEM_Q);                          // [Kn][Cn]
    float* s_s = (float*)(smem + SMEM_S);                         // [Kn][CHUNK]
    unsigned long long* w2_s = (unsigned long long*)(smem + SMEM_W2); // [CHUNK][Kn]
    int* mask_s = (int*)(smem + SMEM_MASK);                       // [CHUNK]

    const int b = blockIdx.x / NSPLIT;
    const int split = blockIdx.x % NSPLIT;
    const int l0 = split * CHUNK;
    const int tid = threadIdx.x;
    const int w = tid >> 5;
    const int lane = tid & 31;

    // Stage queries into smem (float4), mask chunk
    {
        const float4* q4 = (const float4*)q;
        float4* qs4 = (float4*)qs;
        for (int i = tid; i < Kn * Cn / 4; i += THREADS) qs4[i] = q4[i];
        if (tid < CHUNK) mask_s[tid] = mask[b * Ln + l0 + tid];
    }
    __syncthreads();

    const float scale = 0.03125f;  // 1024^-0.5
    const float* xbase = x + ((size_t)b * Ln + l0) * Cn;

    // ---------------- Phase A: scores S[k][l] ----------------
    // warp w owns 16 rows (two groups of 8); k split in two halves of 8.
#pragma unroll
    for (int g = 0; g < 2; ++g) {
        const int l_base = w * 16 + g * 8;
#pragma unroll
        for (int kh = 0; kh < 2; ++kh) {
            unsigned long long p[8][8];
#pragma unroll
            for (int a = 0; a < 8; ++a)
#pragma unroll
                for (int j = 0; j < 8; ++j) p[a][j] = 0ULL;

#pragma unroll
            for (int ci = 0; ci < 8; ++ci) {
                const int c0 = ci * 128 + lane * 4;
                ulonglong2 xv[8];
#pragma unroll
                for (int j = 0; j < 8; ++j)
                    xv[j] = *(const ulonglong2*)(xbase + (size_t)(l_base + j) * Cn + c0);
#pragma unroll
                for (int kk = 0; kk < 8; ++kk) {
                    const int k = kh * 8 + kk;
                    ulonglong2 qv = *(const ulonglong2*)(qs + k * Cn + c0);
#pragma unroll
                    for (int j = 0; j < 8; ++j) {
                        p[kk][j] = fma2(xv[j].x, qv.x, p[kk][j]);
                        p[kk][j] = fma2(xv[j].y, qv.y, p[kk][j]);
                    }
                }
            }
            // fold halves + warp reduce each (k,l) cell
#pragma unroll
            for (int kk = 0; kk < 8; ++kk) {
#pragma unroll
                for (int j = 0; j < 8; ++j) {
                    float2 f = unpack2(p[kk][j]);
                    float s = f.x + f.y;
#pragma unroll
                    for (int off = 16; off; off >>= 1)
                        s += __shfl_down_sync(0xffffffffu, s, off);
                    if (lane == 0) {
                        const int ll = l_base + j;
                        s_s[(kh * 8 + kk) * CHUNK + ll] =
                            mask_s[ll] ? (s * scale) : NEG_INF;
                    }
                }
            }
        }
    }
    __syncthreads();

    // ---------------- Phase B: per-chunk masked softmax stats ----------------
    for (int k = w; k < Kn; k += 8) {
        float v0 = s_s[k * CHUNK + lane];
        float v1 = s_s[k * CHUNK + lane + 32];
        float v2 = s_s[k * CHUNK + lane + 64];
        float v3 = s_s[k * CHUNK + lane + 96];
        float m = fmaxf(fmaxf(v0, v1), fmaxf(v2, v3));
#pragma unroll
        for (int off = 16; off; off >>= 1)
            m = fmaxf(m, __shfl_xor_sync(0xffffffffu, m, off));
        float e0, e1, e2, e3;
        if (m == NEG_INF) {  // whole chunk masked
            e0 = e1 = e2 = e3 = 0.f;
        } else {
            e0 = expf(v0 - m); e1 = expf(v1 - m);
            e2 = expf(v2 - m); e3 = expf(v3 - m);
        }
        float d = e0 + e1 + e2 + e3;
#pragma unroll
        for (int off = 16; off; off >>= 1)
            d += __shfl_xor_sync(0xffffffffu, d, off);
        // store duplicated-pack weights for f32x2 phase C
        w2_s[(lane)      * Kn + k] = pack2(e0, e0);
        w2_s[(lane + 32) * Kn + k] = pack2(e1, e1);
        w2_s[(lane + 64) * Kn + k] = pack2(e2, e2);
        w2_s[(lane + 96) * Kn + k] = pack2(e3, e3);
        if (lane == 0) {
            g_m[(b * NSPLIT + split) * Kn + k] = m;
            g_d[(b * NSPLIT + split) * Kn + k] = d;
        }
    }
    __syncthreads();

    // ---------------- Phase C: partial pooled acc[k][c] ----------------
    const int c0 = tid * 4;  // thread owns 4 consecutive columns
    unsigned long long acc[Kn][2];
#pragma unroll
    for (int k = 0; k < Kn; ++k) { acc[k][0] = 0ULL; acc[k][1] = 0ULL; }

#pragma unroll 2
    for (int l = 0; l < CHUNK; ++l) {
        ulonglong2 xv = *(const ulonglong2*)(xbase + (size_t)l * Cn + c0);
#pragma unroll
        for (int k = 0; k < Kn; ++k) {
            unsigned long long w2 = w2_s[l * Kn + k];  // broadcast
            acc[k][0] = fma2(w2, xv.x, acc[k][0]);
            acc[k][1] = fma2(w2, xv.y, acc[k][1]);
        }
    }
    float* accb = g_acc + ((size_t)(b * NSPLIT + split) * Kn) * Cn;
#pragma unroll
    for (int k = 0; k < Kn; ++k) {
        ulonglong2 v; v.x = acc[k][0]; v.y = acc[k][1];
        *(ulonglong2*)(accb + (size_t)k * Cn + c0) = v;
    }
}

// ---------------- Kernel 2: log-sum-exp merge over splits ----------------
extern "C" __global__ void __launch_bounds__(THREADS)
pool_reduce_kernel(float* __restrict__ out) {
    const int b = blockIdx.x >> 4;
    const int k = blockIdx.x & 15;
    const int tid = threadIdx.x;

    __shared__ float coef[NSPLIT];
    if (tid < NSPLIT) {
        float m = g_m[(b * NSPLIT + tid) * Kn + k];
        float d = g_d[(b * NSPLIT + tid) * Kn + k];
        float M = m;
#pragma unroll
        for (int off = 16; off; off >>= 1)
            M = fmaxf(M, __shfl_xor_sync(0xffffffffu, M, off));
        float t = (m == NEG_INF) ? 0.f : d * expf(m - M);
        float D = t;
#pragma unroll
        for (int off = 16; off; off >>= 1)
            D += __shfl_xor_sync(0xffffffffu, D, off);
        float c = 0.f;
        if (M != NEG_INF && D > 0.f && m != NEG_INF)
            c = expf(m - M) / D;
        coef[tid] = c;   // zero when batch fully masked -> zero output (matches ref)
    }
    __syncthreads();

    const int c0 = tid * 4;
    float4 o = make_float4(0.f, 0.f, 0.f, 0.f);
    const float* accb = g_acc + (size_t)b * NSPLIT * Kn * Cn + (size_t)k * Cn;
#pragma unroll
    for (int s = 0; s < NSPLIT; ++s) {
        float cs = coef[s];
        float4 a = *(const float4*)(accb + (size_t)s * Kn * Cn + c0);
        o.x += cs * a.x; o.y += cs * a.y; o.z += cs * a.z; o.w += cs * a.w;
    }
    *(float4*)(out + ((size_t)(b * Kn + k)) * Cn + c0) = o;
}

extern "C" void kernel_launch(void* const* d_in, const int* in_sizes, int n_in,
                              void* d_out, int out_size) {
    const float* x   = (const float*)d_in[0];
    const int* mask  = (const int*)d_in[1];
    const float* q   = (const float*)d_in[2];
    float* out       = (float*)d_out;

    cudaFuncSetAttribute(pool_partial_kernel,
                         cudaFuncAttributeMaxDynamicSharedMemorySize, SMEM_TOTAL);
    pool_partial_kernel<<<Bn * NSPLIT, THREADS, SMEM_TOTAL>>>(x, mask, q);
    pool_reduce_kernel<<<Bn * Kn, THREADS>>>(out);
}

// round 2
// speedup vs baseline: 3.6284x; 3.6284x over previous
#include <cuda_runtime.h>
#include <math.h>

#define Bn 16
#define Ln 4096
#define Cn 1024
#define Kn 16
#define NSPLIT 32
#define CHUNK 128
#define THREADS 512
#define TC 128          // c-tile width
#define NTILE 8         // Cn / TC
#define QSTRIDE 132     // padded q row stride in floats (2-way conflict cap)
#define NEG_INF (__int_as_float(0xff800000))

// Scratch (__device__ globals per allocation rules)
__device__ float g_acc[(size_t)Bn * NSPLIT * Kn * Cn];   // 32 MB partials
__device__ float g_m[Bn * NSPLIT * Kn];
__device__ float g_d[Bn * NSPLIT * Kn];

// ---- packed dual-fp32 ----
__device__ __forceinline__ unsigned long long fma2(unsigned long long a,
                                                   unsigned long long b,
                                                   unsigned long long c) {
    unsigned long long d;
    asm("fma.rn.f32x2 %0, %1, %2, %3;" : "=l"(d) : "l"(a), "l"(b), "l"(c));
    return d;
}
__device__ __forceinline__ float2 unpack2(unsigned long long v) {
    float2 f;
    f.x = __uint_as_float((unsigned int)(v & 0xffffffffULL));
    f.y = __uint_as_float((unsigned int)(v >> 32));
    return f;
}
__device__ __forceinline__ unsigned long long pack2(float a, float b) {
    unsigned long long v;
    asm("mov.b64 %0, {%1, %2};" : "=l"(v) : "f"(a), "f"(b));
    return v;
}

// ---- cp.async ----
__device__ __forceinline__ void cp_async16(unsigned int smem, const void* g) {
    asm volatile("cp.async.cg.shared.global [%0], [%1], 16;" :: "r"(smem), "l"(g));
}
__device__ __forceinline__ void cp_commit() {
    asm volatile("cp.async.commit_group;");
}
template <int N>
__device__ __forceinline__ void cp_wait() {
    asm volatile("cp.async.wait_group %0;" :: "n"(N));
}

// SMEM byte offsets
#define XS0   0
#define XS1   65536
#define QS0   131072                    // 16 * 132 * 4 = 8448 per buffer
#define QS1   (131072 + 8448)
#define SSOFF (131072 + 16896)          // 147968 : scores [Kn][CHUNK] float
#define W2OFF (SSOFF + Kn * CHUNK * 4)  // 156160 : weights [8 kp][128 l][2] ull
#define MKOFF (W2OFF + CHUNK * Kn * 8)  // 172544 : mask [128] int
#define SMEM_TOTAL (MKOFF + CHUNK * 4)  // 173056

extern "C" __global__ void __launch_bounds__(THREADS, 1)
pool_partial_kernel(const float* __restrict__ x,
                    const int* __restrict__ mask,
                    const float* __restrict__ q) {
    extern __shared__ char smem[];
    unsigned int smem_u32 = (unsigned int)__cvta_generic_to_shared(smem);
    float* s_s = (float*)(smem + SSOFF);
    unsigned long long* w2 = (unsigned long long*)(smem + W2OFF);
    int* mask_s = (int*)(smem + MKOFF);

    const int tid = threadIdx.x;
    const int w = tid >> 5;
    const int lane = tid & 31;
    const int cg = lane & 7;
    const int kg = lane >> 3;
    const int b = blockIdx.x / NSPLIT;
    const int split = blockIdx.x % NSPLIT;
    const int l0 = split * CHUNK;
    const float* xbase = x + ((size_t)b * Ln + l0) * Cn;

    // ---- prefetch tile 0 ----
    {
        unsigned int xd = smem_u32 + XS0;
#pragma unroll
        for (int r = 0; r < 8; ++r) {
            int id = tid + THREADS * r;
            int row = id >> 5, c4 = id & 31;
            cp_async16(xd + row * 512 + c4 * 16,
                       xbase + (size_t)row * Cn + c4 * 4);
        }
        int qrow = tid >> 5, qc4 = tid & 31;
        cp_async16(smem_u32 + QS0 + qrow * (QSTRIDE * 4) + qc4 * 16,
                   q + qrow * Cn + qc4 * 4);
        cp_commit();
    }
    if (tid < CHUNK) mask_s[tid] = mask[b * Ln + l0 + tid];

    unsigned long long acc[8][4];
#pragma unroll
    for (int j = 0; j < 8; ++j)
#pragma unroll
        for (int i = 0; i < 4; ++i) acc[j][i] = 0ULL;

    // ---------------- Phase A: tiled scores ----------------
    for (int t = 0; t < NTILE; ++t) {
        if (t < NTILE - 1) {
            const int tn = t + 1;
            unsigned int xd = smem_u32 + ((tn & 1) ? XS1 : XS0);
#pragma unroll
            for (int r = 0; r < 8; ++r) {
                int id = tid + THREADS * r;
                int row = id >> 5, c4 = id & 31;
                cp_async16(xd + row * 512 + c4 * 16,
                           xbase + (size_t)row * Cn + tn * TC + c4 * 4);
            }
            int qrow = tid >> 5, qc4 = tid & 31;
            cp_async16(smem_u32 + ((tn & 1) ? QS1 : QS0) + qrow * (QSTRIDE * 4) + qc4 * 16,
                       q + qrow * Cn + tn * TC + qc4 * 4);
            cp_commit();
            cp_wait<1>();
        } else {
            cp_wait<0>();
        }
        __syncthreads();

        const float* xs = (const float*)(smem + ((t & 1) ? XS1 : XS0));
        const float* qs = (const float*)(smem + ((t & 1) ? QS1 : QS0));

#pragma unroll
        for (int quad = 0; quad < 4; ++quad) {
            const int cof = cg * 4 + quad * 32;
            ulonglong2 qv[4];
#pragma unroll
            for (int i = 0; i < 4; ++i)
                qv[i] = *(const ulonglong2*)(qs + (kg * 4 + i) * QSTRIDE + cof);
#pragma unroll
            for (int h = 0; h < 2; ++h) {
                ulonglong2 xv[4];
#pragma unroll
                for (int j = 0; j < 4; ++j)
                    xv[j] = *(const ulonglong2*)(xs + (w * 8 + h * 4 + j) * TC + cof);
#pragma unroll
                for (int j = 0; j < 4; ++j)
#pragma unroll
                    for (int i = 0; i < 4; ++i) {
                        acc[h * 4 + j][i] = fma2(xv[j].x, qv[i].x, acc[h * 4 + j][i]);
                        acc[h * 4 + j][i] = fma2(xv[j].y, qv[i].y, acc[h * 4 + j][i]);
                    }
            }
        }
        __syncthreads();
    }

    // ---- fold + 3-step cgroup reduction + masked write ----
    {
        const float scale = 0.03125f;
#pragma unroll
        for (int j = 0; j < 8; ++j)
#pragma unroll
            for (int i = 0; i < 4; ++i) {
                float2 f = unpack2(acc[j][i]);
                float s = f.x + f.y;
                s += __shfl_xor_sync(0xffffffffu, s, 1);
                s += __shfl_xor_sync(0xffffffffu, s, 2);
                s += __shfl_xor_sync(0xffffffffu, s, 4);
                if (cg == 0) {
                    const int l = w * 8 + j;
                    const int k = kg * 4 + i;
                    s_s[k * CHUNK + l] = mask_s[l] ? (s * scale) : NEG_INF;
                }
            }
    }
    __syncthreads();

    // ---------------- Phase B: softmax stats (warp w <-> k) ----------------
    {
        const int k = w;
        float v0 = s_s[k * CHUNK + lane];
        float v1 = s_s[k * CHUNK + lane + 32];
        float v2 = s_s[k * CHUNK + lane + 64];
        float v3 = s_s[k * CHUNK + lane + 96];
        float m = fmaxf(fmaxf(v0, v1), fmaxf(v2, v3));
#pragma unroll
        for (int off = 16; off; off >>= 1)
            m = fmaxf(m, __shfl_xor_sync(0xffffffffu, m, off));
        float e0, e1, e2, e3;
        if (m == NEG_INF) {
            e0 = e1 = e2 = e3 = 0.f;
        } else {
            e0 = __expf(v0 - m); e1 = __expf(v1 - m);
            e2 = __expf(v2 - m); e3 = __expf(v3 - m);
        }
        float d = e0 + e1 + e2 + e3;
#pragma unroll
        for (int off = 16; off; off >>= 1)
            d += __shfl_xor_sync(0xffffffffu, d, off);
        // layout: w2[kp*256 + l*2 + (k&1)]  (k-pair interleave for LDS.128)
        const int base = (k >> 1) * 256 + (k & 1);
        w2[base + (lane)       * 2] = pack2(e0, e0);
        w2[base + (lane + 32)  * 2] = pack2(e1, e1);
        w2[base + (lane + 64)  * 2] = pack2(e2, e2);
        w2[base + (lane + 96)  * 2] = pack2(e3, e3);
        if (lane == 0) {
            g_m[(b * NSPLIT + split) * Kn + k] = m;
            g_d[(b * NSPLIT + split) * Kn + k] = d;
        }
    }
    __syncthreads();

    // ---------------- Phase C: weighted accumulation ----------------
    {
        const int c0 = tid * 2;  // thread owns a c-pair
        unsigned long long acc2[Kn];
#pragma unroll
        for (int k = 0; k < Kn; ++k) acc2[k] = 0ULL;

#pragma unroll 2
        for (int l = 0; l < CHUNK; l += 4) {
            unsigned long long xv[4];
#pragma unroll
            for (int u = 0; u < 4; ++u)
                xv[u] = *(const unsigned long long*)(xbase + (size_t)(l + u) * Cn + c0);
#pragma unroll
            for (int u = 0; u < 4; ++u) {
#pragma unroll
                for (int kp = 0; kp < 8; ++kp) {
                    ulonglong2 wp = *(const ulonglong2*)&w2[kp * 256 + (l + u) * 2];
                    acc2[2 * kp]     = fma2(wp.x, xv[u], acc2[2 * kp]);
                    acc2[2 * kp + 1] = fma2(wp.y, xv[u], acc2[2 * kp + 1]);
                }
            }
        }
        float* ab = g_acc + ((size_t)(b * NSPLIT + split) * Kn) * Cn;
#pragma unroll
        for (int k = 0; k < Kn; ++k)
            *(unsigned long long*)(ab + (size_t)k * Cn + c0) = acc2[k];
    }
}

// ---------------- Kernel 2: LSE merge (1024 blocks, 4 c-quarters) ----------------
extern "C" __global__ void __launch_bounds__(128)
pool_reduce_kernel(float* __restrict__ out) {
    const int bk = blockIdx.x >> 2;
    const int b = bk >> 4;
    const int k = bk & 15;
    const int cq = blockIdx.x & 3;
    const int tid = threadIdx.x;

    __shared__ float coef[NSPLIT];
    if (tid < NSPLIT) {
        float m = g_m[(b * NSPLIT + tid) * Kn + k];
        float d = g_d[(b * NSPLIT + tid) * Kn + k];
        float M = m;
#pragma unroll
        for (int off = 16; off; off >>= 1)
            M = fmaxf(M, __shfl_xor_sync(0xffffffffu, M, off));
        float t = (m == NEG_INF) ? 0.f : d * __expf(m - M);
        float D = t;
#pragma unroll
        for (int off = 16; off; off >>= 1)
            D += __shfl_xor_sync(0xffffffffu, D, off);
        float c = 0.f;
        if (M != NEG_INF && D > 0.f)
            c = __expf(m - M) / D;   // m == -inf -> expf(-inf) = 0
        coef[tid] = c;
    }
    __syncthreads();

    const int c0 = cq * 256 + tid * 2;
    unsigned long long o = 0ULL;
    const float* accb = g_acc + ((size_t)b * NSPLIT * Kn + k) * Cn;
#pragma unroll
    for (int s = 0; s < NSPLIT; ++s) {
        unsigned long long cs = pack2(coef[s], coef[s]);
        unsigned long long a = *(const unsigned long long*)(accb + (size_t)s * Kn * Cn + c0);
        o = fma2(cs, a, o);
    }
    *(unsigned long long*)(out + ((size_t)(b * Kn + k)) * Cn + c0) = o;
}

extern "C" void kernel_launch(void* const* d_in, const int* in_sizes, int n_in,
                              void* d_out, int out_size) {
    const float* x  = (const float*)d_in[0];
    const int* mask = (const int*)d_in[1];
    const float* q  = (const float*)d_in[2];
    float* out      = (float*)d_out;

    cudaFuncSetAttribute(pool_partial_kernel,
                         cudaFuncAttributeMaxDynamicSharedMemorySize, SMEM_TOTAL);
    pool_partial_kernel<<<Bn * NSPLIT, THREADS, SMEM_TOTAL>>>(x, mask, q);
    pool_reduce_kernel<<<Bn * Kn * 4, 128>>>(out);
}